// round 8
// baseline (speedup 1.0000x reference)
#include <cuda_runtime.h>
#include <cuda_bf16.h>

#define KDIM  64
#define LOG2E 1.4426950408889634f
#define LN2   0.6931471805599453f
#define RPC   4          // rows per CTA (2 warps each)
#define DIST  4          // emit prefetch distance (steps), power of 2
#define TH    -1000000.0f
#define FULL  0xffffffffu

__device__ __forceinline__ unsigned long long pk2(float a, float b) {
    unsigned long long r;
    asm("mov.b64 %0, {%1, %2};" : "=l"(r) : "f"(a), "f"(b));
    return r;
}
__device__ __forceinline__ unsigned long long fma2(unsigned long long a, unsigned long long b,
                                                   unsigned long long c) {
    unsigned long long d;
    asm("fma.rn.f32x2 %0, %1, %2, %3;" : "=l"(d) : "l"(a), "l"(b), "l"(c));
    return d;
}
__device__ __forceinline__ unsigned long long add2(unsigned long long a, unsigned long long b) {
    unsigned long long d;
    asm("add.rn.f32x2 %0, %1, %2;" : "=l"(d) : "l"(a), "l"(b));
    return d;
}
__device__ __forceinline__ float ex2f(float x) {
    float y; asm("ex2.approx.f32 %0, %1;" : "=f"(y) : "f"(x)); return y;
}
__device__ __forceinline__ float lg2f(float x) {
    float y; asm("lg2.approx.f32 %0, %1;" : "=f"(y) : "f"(x)); return y;
}
__device__ __forceinline__ float scalbn_fast(float x, int d) {
    return __int_as_float(__float_as_int(x) - (d << 23));
}
__device__ __forceinline__ void barrow(int id) {   // named barrier, 64 threads (one row)
    asm volatile("bar.sync %0, 64;" :: "r"(id) : "memory");
}

// TWO WARPS per batch row; each lane owns ONE state (st = half*32 + lane).
// Exp-domain recursion (no per-step lg2/ex2):
//   e_j(t) = [ m_t ? (sum_i e_i(t-1) E[i][j]) * 2^(emit_j lg2e) : e_j(t-1) ] * 2^(-d)
// d = exponent(e_0) renorm (integer, exact); alpha2 = C2i + lg2(e_j).
// One named barrier per row per step. Mask votes are cross-warp via a 4-DEEP smem
// flag ring indexed by step mod 4: flags for step T+1 are written pre-barrier(T),
// consumed post-barrier(T+1) -> writer and any aliasing reader are separated by
// >=1 barrier in both directions (2-deep was racy). Dummy steps t>=N run masked.
__global__ __launch_bounds__(64 * RPC, 1) void crf_fwd_kernel(
    const float* __restrict__ y_pred,   // [B, N, K]
    const float* __restrict__ trans,    // [K, K]
    const int*   __restrict__ y_true,   // [B, N]
    float*       __restrict__ out,      // [B]
    int N, int B)
{
    __shared__ float sh_trans[KDIM * KDIM];
    __shared__ __align__(16) float sh_e[RPC][2][KDIM];
    __shared__ int sh_di[RPC][2];
    __shared__ unsigned sh_mv[RPC][2][4];   // [row][half][step & 3] mask votes
    __shared__ float sh_red[RPC][2][2];     // [row][half][{se,point}]

    const int tid  = threadIdx.x;
    const int lane = tid & 31;
    const int wid  = tid >> 5;
    const int r    = wid >> 1;          // row within CTA (0..3)
    const int half = wid & 1;           // which 32-state half
    const int row  = blockIdx.x * RPC + r;
    const int bid  = 1 + r;             // named barrier id for this row

    for (int i = tid; i < KDIM * KDIM; i += 64 * RPC) sh_trans[i] = trans[i];
    __syncthreads();
    if (row >= B) return;

    const int st = half * 32 + lane;    // my state (column of E)

    // My E column: Ec[k] packs rows (2k, 2k+1), k = 0..31.
    unsigned long long Ec[KDIM / 2];
#pragma unroll
    for (int k = 0; k < KDIM / 2; ++k) {
        Ec[k] = pk2(__expf(sh_trans[(2 * k) * KDIM + st]),
                    __expf(sh_trans[(2 * k + 1) * KDIM + st]));
    }

    const float* yrow = y_pred + (size_t)row * N * KDIM;
    const int*   trow = y_true + (size_t)row * N;

    // ---- t = 0 ----
    float y0 = yrow[st];
    int yt0 = trow[0];
    unsigned v0 = __all_sync(FULL, y0 > TH);
    sh_mv[r][half][0] = v0;
    float e = 0.0f;
    float point = 0.0f;
    int   C2i = 0;
    float tv = 0.0f;

    // ---- prime pipelines ----
    float ring[DIST];
#pragma unroll
    for (int p = 1; p <= DIST; ++p) {
        int tt = (p < N) ? p : (N - 1);
        ring[p & (DIST - 1)] = yrow[(size_t)tt * KDIM + st];
    }
    // votes for step 1 into slot 1
    unsigned v1 = __all_sync(FULL, ring[1 & (DIST - 1)] > TH);
    sh_mv[r][half][1] = (1 < N) ? v1 : 0u;
    __syncthreads();                    // publishes vote slots 0 and 1

    {   // finish t = 0 with the combined mask
        unsigned m0 = sh_mv[r][0][0] & sh_mv[r][1][0];
        float fm0 = m0 ? 1.0f : 0.0f;
        e = ex2f((y0 * fm0) * LOG2E);
        point = (st == yt0) ? y0 * fm0 : 0.0f;
        sh_e[r][0][st] = e;
        if (half == 0 && lane == 0)
            sh_di[r][0] = (int)((unsigned)__float_as_int(e) >> 23) - 127;
    }
    float fmprev = (sh_mv[r][0][0] & sh_mv[r][1][0]) ? 1.0f : 0.0f;

    int yt_cur = trow[(1 < N) ? 1 : (N - 1)];
    int yt_nx  = trow[(2 < N) ? 2 : (N - 1)];
    float trv_cur = sh_trans[yt0 * KDIM + yt_cur];
    __syncthreads();                    // t=0 e-stores + di visible before loop

    // MS  = T & 3 (this step's vote slot), MSN = (T+1) & 3 (next step's slot)
#define STEP(T, RP, RPN, BUF, PBUF, MS, MSN)                                         \
    {                                                                                \
        float yv = ring[RP];                                                         \
        int tt = ((T) + DIST < N) ? ((T) + DIST) : (N - 1);                          \
        ring[RP] = yrow[(size_t)tt * KDIM + st];                                     \
        unsigned vn = __all_sync(FULL, ring[RPN] > TH);                              \
        sh_mv[r][half][MSN] = ((T) + 1 < N) ? vn : 0u;  /* flags for step T+1 */     \
        int tn = ((T) + 2 < N) ? ((T) + 2) : (N - 1);                                \
        int yt_nx2 = trow[tn];                                                       \
        float trv_next = sh_trans[yt_cur * KDIM + yt_nx];                            \
        barrow(bid);   /* publishes e(t-1), d(t-1), flags for t */                   \
        unsigned mcur = sh_mv[r][0][MS] & sh_mv[r][1][MS];                           \
        int d = sh_di[r][PBUF];                                                      \
        float fmcur = mcur ? 1.0f : 0.0f;                                            \
        float p = ex2f(yv * (fmcur * LOG2E));  /* MUFU under the dot */              \
        unsigned long long A0 = 0, A1 = 0, A2 = 0, A3 = 0;                           \
        const ulonglong2* ep = (const ulonglong2*)sh_e[r][PBUF];                     \
        _Pragma("unroll")                                                            \
        for (int k = 0; k < KDIM / 4; ++k) {                                         \
            ulonglong2 ee = ep[k];                                                   \
            if (k & 1) { A2 = fma2(ee.x, Ec[2 * k], A2);                             \
                         A3 = fma2(ee.y, Ec[2 * k + 1], A3); }                       \
            else       { A0 = fma2(ee.x, Ec[2 * k], A0);                             \
                         A1 = fma2(ee.y, Ec[2 * k + 1], A1); }                       \
        }                                                                            \
        unsigned long long AA = add2(add2(A0, A1), add2(A2, A3));                    \
        float alo, ahi;                                                              \
        asm("mov.b64 {%0, %1}, %2;" : "=f"(alo), "=f"(ahi) : "l"(AA));               \
        float q = mcur ? (alo + ahi) * p : e;                                        \
        e = scalbn_fast(q, d);                                                       \
        C2i += d;                                                                    \
        point += (st == yt_cur) ? yv * fmcur : 0.0f;                                 \
        tv += trv_cur * (fmprev * fmcur);                                            \
        if (half == 0 && lane == 0)                                                  \
            sh_di[r][BUF] = (int)((unsigned)__float_as_int(e) >> 23) - 127;          \
        sh_e[r][BUF][st] = e;                                                        \
        fmprev = fmcur;                                                              \
        trv_cur = trv_next; yt_cur = yt_nx; yt_nx = yt_nx2;                          \
    }

    // ---- main loop: t0 === 1 (mod 4); overflow steps are harmless dummy steps ----
    for (int t0 = 1; t0 < N; t0 += 4) {
        STEP(t0 + 0, 1, 2, 1, 0, 1, 2)
        STEP(t0 + 1, 2, 3, 0, 1, 2, 3)
        STEP(t0 + 2, 3, 0, 1, 0, 3, 0)
        STEP(t0 + 3, 0, 1, 0, 1, 0, 1)
    }
#undef STEP

    // ---- epilogue: reduce 2^(w) and point across the 2 warps of this row ----
    float se = e, pp = point;
#pragma unroll
    for (int o = 16; o > 0; o >>= 1) {
        se += __shfl_xor_sync(FULL, se, o);
        pp += __shfl_xor_sync(FULL, pp, o);
    }
    if (lane == 0) { sh_red[r][half][0] = se; sh_red[r][half][1] = pp; }
    barrow(bid);
    if (half == 0 && lane == 0) {
        float seT = sh_red[r][0][0] + sh_red[r][1][0];
        float ppT = sh_red[r][0][1] + sh_red[r][1][1];
        out[row] = LN2 * ((float)C2i + lg2f(seT)) - (ppT + tv);
    }
}

extern "C" void kernel_launch(void* const* d_in, const int* in_sizes, int n_in,
                              void* d_out, int out_size) {
    const float* y_pred = (const float*)d_in[0];   // [B, N, K] f32
    const float* trans  = (const float*)d_in[1];   // [K, K]    f32
    const int*   y_true = (const int*)  d_in[2];   // [B, N]    i32
    float* out = (float*)d_out;                    // [B]       f32

    int B = out_size;                  // 512
    int N = in_sizes[2] / B;           // 1024
    int blocks = (B + RPC - 1) / RPC;  // 128
    crf_fwd_kernel<<<blocks, 64 * RPC>>>(y_pred, trans, y_true, out, N, B);
}